// round 6
// baseline (speedup 1.0000x reference)
#include <cuda_runtime.h>
#include <cuda_bf16.h>

// Problem constants
#define BB 64
#define LL 128
#define HH 1024
#define TT 256
#define NG 4096          // 4*H gate rows

// Persistent kernel config
#define NBLK 128         // blocks; each owns 8 hidden units (32 gate rows)
#define NTHR 256
#define JPB 8            // hidden units per block
#define ROWS 32          // gate rows per block = 4*JPB
#define KC 128           // k-chunk staged in smem
#define NCHUNK (HH / KC) // 8
#define WSTRIDE 1025     // padded row stride for W slice in smem (odd -> bank spread)

// smem layout (in floats)
#define WS_OFF 0
#define WS_SZ  (ROWS * WSTRIDE)          // 32800
#define HS_OFF (WS_OFF + WS_SZ)          // 32800
#define HS_SZ  (2 * KC * BB)             // 16384 (double buffer)
#define XG_OFF (HS_OFF + HS_SZ)          // 49184
#define XG_SZ  (ROWS * BB)               // 2048
#define GB_OFF (XG_OFF + XG_SZ)          // 51232
#define GB_STRIDE 66
#define GB_SZ  (ROWS * GB_STRIDE)        // 2112
#define CS_OFF (GB_OFF + GB_SZ)          // 53344
#define CS_SZ  (JPB * BB)                // 512
#define HN_OFF (CS_OFF + CS_SZ)          // 53856
#define HN_SZ  (JPB * BB)                // 512
#define WO_OFF (HN_OFF + HN_SZ)          // 54368
#define SMEM_FLOATS (WO_OFF + 8)         // 54376
#define SMEM_BYTES (SMEM_FLOATS * 4)     // 217504 bytes

// Device scratch (static allocation is the sanctioned mechanism)
__device__ float g_hidden[BB * HH];              // [b][k]
__device__ float g_xg[NG * BB];                  // [gate_row][b]
__device__ float g_h[2 * HH * BB];               // ping-pong h, [unit][b]
__device__ float g_partial[NBLK * TT * BB];      // per-block output partials
__device__ unsigned g_arrive;
__device__ unsigned g_release;

// ---------- helpers ----------
__device__ __forceinline__ unsigned long long pack2(float a) {
    unsigned long long r;
    asm("mov.b64 %0, {%1, %1};" : "=l"(r) : "f"(a));
    return r;
}
__device__ __forceinline__ void fma2(unsigned long long& acc,
                                     unsigned long long a, unsigned long long b) {
    asm("fma.rn.f32x2 %0, %1, %2, %0;" : "+l"(acc) : "l"(a), "l"(b));
}
__device__ __forceinline__ void cp16(void* smem_dst, const void* gsrc) {
    unsigned sa = (unsigned)__cvta_generic_to_shared(smem_dst);
    asm volatile("cp.async.cg.shared.global [%0], [%1], 16;" :: "r"(sa), "l"(gsrc));
}
__device__ __forceinline__ void cp_commit() {
    asm volatile("cp.async.commit_group;");
}
__device__ __forceinline__ float sigm(float x) { return 1.0f / (1.0f + expf(-x)); }

// ---------- K0: zero the h buffers + barrier counters ----------
__global__ void k0_init() {
    int g = blockIdx.x * blockDim.x + threadIdx.x;
    if (g < 2 * HH * BB) g_h[g] = 0.0f;
    if (g == 0) { g_arrive = 0u; g_release = 0u; }
}

// ---------- K1: hidden[b][k] = latent[b] . W_lin[k] + b_lin[k] ----------
__global__ void k1_hidden(const float* __restrict__ latent,
                          const float* __restrict__ W_lin,
                          const float* __restrict__ b_lin) {
    int g = blockIdx.x * blockDim.x + threadIdx.x;   // 65536 threads
    int k = g >> 6;
    int b = g & 63;
    float acc = b_lin[k];
    const float* lr = latent + b * LL;
    const float* wr = W_lin + k * LL;
#pragma unroll 8
    for (int l = 0; l < LL; ++l) acc += lr[l] * wr[l];
    g_hidden[b * HH + k] = acc;
}

// ---------- K2: x_gates[r][b] = hidden[b] . W_ih[r] + b_ih[r] + b_hh[r] ----------
__global__ void k2_xgates(const float* __restrict__ W_ih,
                          const float* __restrict__ b_ih,
                          const float* __restrict__ b_hh) {
    int tid = threadIdx.x;
    int r = blockIdx.x * 4 + (tid >> 6);   // 1024 blocks x 4 rows
    int b = tid & 63;
    float acc = b_ih[r] + b_hh[r];
    const float* hr = g_hidden + b * HH;
    const float* wr = W_ih + r * HH;
#pragma unroll 8
    for (int k = 0; k < HH; ++k) acc += hr[k] * wr[k];
    g_xg[r * BB + b] = acc;
}

// ---------- K3: persistent LSTM recurrence ----------
__global__ void __launch_bounds__(NTHR, 1)
k3_lstm(const float* __restrict__ W_hh, const float* __restrict__ W_out) {
    extern __shared__ float sm[];
    float* ws = sm + WS_OFF;
    float* hs = sm + HS_OFF;
    float* xg = sm + XG_OFF;
    float* gb = sm + GB_OFF;
    float* cs = sm + CS_OFF;
    float* hn = sm + HN_OFF;
    float* wo = sm + WO_OFF;
    float* red = hs;  // 8*2048 reduction buffer aliases hs after GEMM

    const int tid = threadIdx.x;
    const int blk = blockIdx.x;
    const int j0 = blk * JPB;

    // warp = k-slice; lane -> (rt, bt)
    const int s  = tid >> 5;        // 0..7 : k residue class
    const int lane = tid & 31;
    const int rt = lane >> 3;       // 0..3 : row tile (8 rows)
    const int bt = lane & 7;        // 0..7 : batch tile (8 batches)
    const int rt8 = rt * 8;

    // ---- load W_hh slice (32 rows) into smem, once ----
    for (int idx = tid; idx < ROWS * HH; idx += NTHR) {
        int row = idx >> 10;
        int k = idx & (HH - 1);
        int gate = row >> 3, jl = row & 7;
        ws[row * WSTRIDE + k] = W_hh[(gate * HH + j0 + jl) * HH + k];
    }
    // ---- load x_gates slice ----
    for (int idx = tid; idx < ROWS * BB; idx += NTHR) {
        int row = idx >> 6;
        int b = idx & 63;
        int gate = row >> 3, jl = row & 7;
        xg[row * BB + b] = g_xg[(gate * HH + j0 + jl) * BB + b];
    }
    cs[tid] = 0.0f;
    cs[tid + 256] = 0.0f;
    if (tid < JPB) wo[tid] = W_out[j0 + tid];
    __syncthreads();

    for (int t = 0; t < TT; ++t) {
        const float* hread = g_h + (t & 1) * (HH * BB);
        float* hwrite = g_h + ((t & 1) ^ 1) * (HH * BB);

        // prefetch chunk 0
        {
            const float* src = hread;
            float* dst = hs;
#pragma unroll
            for (int i = 0; i < 8; ++i)
                cp16(dst + (tid + i * 256) * 4, src + (tid + i * 256) * 4);
            cp_commit();
        }

        // init accumulators (warp 0 seeds with x_gates; others zero)
        unsigned long long acc[8][4];
#pragma unroll
        for (int i = 0; i < 8; ++i) {
            if (s == 0) {
                const float* xp = xg + (rt8 + i) * BB + bt * 8;
                ulonglong2 x01 = *(const ulonglong2*)xp;
                ulonglong2 x23 = *(const ulonglong2*)(xp + 4);
                acc[i][0] = x01.x; acc[i][1] = x01.y;
                acc[i][2] = x23.x; acc[i][3] = x23.y;
            } else {
                acc[i][0] = 0ull; acc[i][1] = 0ull; acc[i][2] = 0ull; acc[i][3] = 0ull;
            }
        }

        for (int c = 0; c < NCHUNK; ++c) {
            if (c < NCHUNK - 1) {
                const float* src = hread + (c + 1) * KC * BB;
                float* dst = hs + ((c + 1) & 1) * (KC * BB);
#pragma unroll
                for (int i = 0; i < 8; ++i)
                    cp16(dst + (tid + i * 256) * 4, src + (tid + i * 256) * 4);
                cp_commit();
                asm volatile("cp.async.wait_group 1;");
            } else {
                asm volatile("cp.async.wait_group 0;");
            }
            __syncthreads();

            const float* hc = hs + (c & 1) * (KC * BB);
            const int kg0 = c * KC + s;
#pragma unroll
            for (int m = 0; m < 16; ++m) {
                const int kl = s + m * 8;       // local k in chunk
                const int kg = kg0 + m * 8;     // global k (for W)
                const float* hp = hc + kl * BB + bt * 8;
                ulonglong2 h01 = *(const ulonglong2*)hp;
                ulonglong2 h23 = *(const ulonglong2*)(hp + 4);
#pragma unroll
                for (int i = 0; i < 8; ++i) {
                    unsigned long long w2 = pack2(ws[(rt8 + i) * WSTRIDE + kg]);
                    fma2(acc[i][0], w2, h01.x);
                    fma2(acc[i][1], w2, h01.y);
                    fma2(acc[i][2], w2, h23.x);
                    fma2(acc[i][3], w2, h23.y);
                }
            }
            __syncthreads();
        }

        // dump per-slice partials into red[s][r*64+b] (aliases hs; GEMM done)
#pragma unroll
        for (int i = 0; i < 8; ++i) {
            float* rp = red + s * (ROWS * BB) + (rt8 + i) * BB + bt * 8;
#pragma unroll
            for (int p = 0; p < 4; ++p)
                *(unsigned long long*)(rp + 2 * p) = acc[i][p];
        }
        __syncthreads();

        // reduce 8 slices -> gates in gb
#pragma unroll
        for (int j = 0; j < 8; ++j) {
            int o = tid + j * 256;
            float ssum = 0.0f;
#pragma unroll
            for (int sl = 0; sl < 8; ++sl) ssum += red[sl * (ROWS * BB) + o];
            int r = o >> 6, b = o & 63;
            gb[r * GB_STRIDE + b] = ssum;
        }
        __syncthreads();

        // elementwise LSTM update (512 elems, 2 per thread)
#pragma unroll
        for (int q = 0; q < 2; ++q) {
            int e = tid + q * 256;
            int jl = e >> 6, b = e & 63;
            float gi = sigm(gb[(jl)          * GB_STRIDE + b]);
            float gf = sigm(gb[(8 + jl)      * GB_STRIDE + b]);
            float gg = tanhf(gb[(16 + jl)    * GB_STRIDE + b]);
            float go = sigm(gb[(24 + jl)     * GB_STRIDE + b]);
            float cn = gf * cs[jl * BB + b] + gi * gg;
            cs[jl * BB + b] = cn;
            float hv = go * tanhf(cn);
            hwrite[(j0 + jl) * BB + b] = hv;
            hn[jl * BB + b] = hv;
        }
        __syncthreads();

        // per-block output partial for this timestep
        if (tid < BB) {
            float po = 0.0f;
#pragma unroll
            for (int jl = 0; jl < JPB; ++jl) po += hn[jl * BB + tid] * wo[jl];
            g_partial[(blk * TT + t) * BB + tid] = po;
        }
        __threadfence();
        __syncthreads();

        // grid barrier (monotonic counters, reset by K0 each launch)
        if (tid == 0) {
            unsigned tgt = (unsigned)(t + 1);
            unsigned arr = atomicAdd(&g_arrive, 1u) + 1u;
            if (arr == (unsigned)NBLK * tgt) {
                atomicExch(&g_release, tgt);
            } else {
                while (*(volatile unsigned*)&g_release < tgt) { }
            }
            __threadfence();
        }
        __syncthreads();
    }
}

// ---------- K4: reduce partials -> out[b][t] ----------
__global__ void k4_out(const float* __restrict__ b_out, float* __restrict__ out) {
    int g = blockIdx.x * blockDim.x + threadIdx.x;   // 16384 threads
    int b = g & 63;
    int t = g >> 6;
    float acc = b_out[0];
#pragma unroll 8
    for (int blk = 0; blk < NBLK; ++blk)
        acc += g_partial[(blk * TT + t) * BB + b];
    out[b * TT + t] = acc;
}

extern "C" void kernel_launch(void* const* d_in, const int* in_sizes, int n_in,
                              void* d_out, int out_size) {
    const float* latent = (const float*)d_in[0];
    const float* W_lin  = (const float*)d_in[1];
    const float* b_lin  = (const float*)d_in[2];
    const float* W_ih   = (const float*)d_in[3];
    const float* W_hh   = (const float*)d_in[4];
    const float* b_ih   = (const float*)d_in[5];
    const float* b_hh   = (const float*)d_in[6];
    const float* W_out  = (const float*)d_in[7];
    const float* b_out  = (const float*)d_in[8];
    float* out = (float*)d_out;

    cudaFuncSetAttribute(k3_lstm, cudaFuncAttributeMaxDynamicSharedMemorySize, SMEM_BYTES);

    k0_init<<<512, 256>>>();
    k1_hidden<<<(BB * HH) / 256, 256>>>(latent, W_lin, b_lin);
    k2_xgates<<<NG / 4, 256>>>(W_ih, b_ih, b_hh);
    k3_lstm<<<NBLK, NTHR, SMEM_BYTES>>>(W_hh, W_out);
    k4_out<<<(BB * TT) / 256, 256>>>(b_out, out);
}